// round 3
// baseline (speedup 1.0000x reference)
#include <cuda_runtime.h>

// ============================================================================
// Layer_70411693850653 — equivariant GNN layer, fully fused.
//
//  * messages[384:640] never consumed -> skipped
//  * agg == 1.5 * feats[:, :128] -> skip connection folded into weights
//  * scatter_mean via bucketed inverse-CSR + register gather (no float atomics)
//  * NEW: prepass transposes nf into interleaved float4 {f0,g0,g1,g2} per
//    (node,channel) -> Phase A does ONE coalesced LDG.128 per edge
//  * Phase B: f32x2 FMA with weights PRE-PACKED as float2 in smem (no MOVs)
// ============================================================================

#define N_MAX 50000
#define CAP   32
#define TILE  16
#define FS    384
#define NBLK  592

__device__ int    g_deg[N_MAX];            // zero-init at load; k_main resets
__device__ int    g_bucket[N_MAX * CAP];
__device__ float4 g_nfT[N_MAX * 32];       // [n][lane] = {f0, g0, g1, g2}

// ---------------------------------------------------------------------------
__global__ void k_fill(const int* __restrict__ recv, int E) {
    int e = blockIdx.x * blockDim.x + threadIdx.x;
    if (e < E) {
        int r = recv[e];
        int slot = atomicAdd(&g_deg[r], 1);
        if (slot < CAP) g_bucket[r * CAP + slot] = e;
    }
}

// ---------------------------------------------------------------------------
// Transpose nf rows into interleaved layout. One warp per node.
__global__ __launch_bounds__(256) void k_transpose(const float* __restrict__ nf, int N) {
    __shared__ float buf[8][128];
    const int w = threadIdx.x >> 5, lane = threadIdx.x & 31;
    const int n = blockIdx.x * 8 + w;
    if (n >= N) return;
    reinterpret_cast<float4*>(buf[w])[lane] =
        reinterpret_cast<const float4*>(nf + (size_t)n * 128)[lane];
    __syncwarp();
    float4 v;
    v.x = buf[w][lane];
    v.y = buf[w][32 + 3 * lane];
    v.z = buf[w][33 + 3 * lane];
    v.w = buf[w][34 + 3 * lane];
    g_nfT[n * 32 + lane] = v;
}

// ---------------------------------------------------------------------------
__device__ __forceinline__ void fma2(unsigned long long& acc,
                                     unsigned long long a,
                                     unsigned long long b) {
    asm("fma.rn.f32x2 %0, %1, %2, %0;" : "+l"(acc) : "l"(a), "l"(b));
}
__device__ __forceinline__ float2 unpack2(unsigned long long v) {
    float2 f;
    asm("mov.b64 {%0, %1}, %2;" : "=f"(f.x), "=f"(f.y) : "l"(v));
    return f;
}

// ---------------------------------------------------------------------------
__global__ __launch_bounds__(256) void k_main(
    const float* __restrict__ sh,
    const int*   __restrict__ senders,
    const float* __restrict__ W0, const float* __restrict__ W1,
    const float* __restrict__ Ws0, const float* __restrict__ Ws1,
    float* __restrict__ out, int N)
{
    // weights stored as 48 pairs x 32 lanes of float2 (pair over the u dim)
    __shared__ __align__(16) float2 sW0p[48 * 32];
    __shared__ __align__(16) float2 sW1p[48 * 32];
    __shared__ __align__(16) float  sF[TILE * FS];

    const float invA = 0.10206207261596575f;         // 1/sqrt(96)
    const float cB   = 1.5f * 0.17677669529663687f;  // 1.5/sqrt(32)
    const float INV_SQRT3 = 0.5773502691896258f;

    const int t    = threadIdx.x;
    const int w    = t >> 5;
    const int lane = t & 31;

    // Build effective weights, pre-packed in pairs over u
    for (int idx = t; idx < 48 * 32; idx += 256) {
        int p = idx >> 5, l = idx & 31;
        int u0 = 2 * p, u1 = 2 * p + 1;
        float a0 = W0[u0 * 32 + l] * invA, a1 = W0[u1 * 32 + l] * invA;
        float b0 = W1[u0 * 32 + l] * invA, b1 = W1[u1 * 32 + l] * invA;
        if (u0 < 32) { a0 = fmaf(cB, Ws0[u0 * 32 + l], a0);
                       b0 = fmaf(cB, Ws1[u0 * 32 + l], b0); }
        if (u1 < 32) { a1 = fmaf(cB, Ws0[u1 * 32 + l], a1);
                       b1 = fmaf(cB, Ws1[u1 * 32 + l], b1); }
        sW0p[idx] = make_float2(a0, a1);
        sW1p[idx] = make_float2(b0, b1);
    }

    const int ntiles = (N + TILE - 1) / TILE;
    for (int tile = blockIdx.x; tile < ntiles; tile += gridDim.x) {
        __syncthreads();   // protect sF against previous iteration's readers

        // ---------------- Phase A: gather + TP means -----------------------
        #pragma unroll
        for (int half = 0; half < 2; half++) {
            const int ni = half * 8 + w;
            const int n  = tile * TILE + ni;

            float a0 = 0.f, ax = 0.f, ay = 0.f, az = 0.f;
            float p00 = 0.f, dot = 0.f;
            float qx = 0.f, qy = 0.f, qz = 0.f;   // p01 = s0*f1
            float rx = 0.f, ry = 0.f, rz = 0.f;   // p10 = f0*s1

            int d = 0;
            if (n < N) d = g_deg[n];
            const int dc = min(d, CAP);
            if (n < N && lane == 0) g_deg[n] = 0;   // maintain zero-invariant

            int    my_s  = 0;
            float4 my_sh = make_float4(0.f, 0.f, 0.f, 0.f);
            if (lane < dc) {
                int e  = g_bucket[n * CAP + lane];
                my_s   = senders[e];
                my_sh  = *reinterpret_cast<const float4*>(sh + (size_t)e * 4);
            }

            for (int j = 0; j < dc; j++) {
                int   s   = __shfl_sync(0xffffffffu, my_s,    j);
                float s0  = __shfl_sync(0xffffffffu, my_sh.x, j);
                float s1x = __shfl_sync(0xffffffffu, my_sh.y, j);
                float s1y = __shfl_sync(0xffffffffu, my_sh.z, j);
                float s1z = __shfl_sync(0xffffffffu, my_sh.w, j);

                float4 v = g_nfT[s * 32 + lane];   // one coalesced LDG.128
                float f0 = v.x, g0 = v.y, g1 = v.z, g2 = v.w;

                a0 += f0; ax += g0; ay += g1; az += g2;
                p00 = fmaf(s0, f0, p00);
                dot = fmaf(s1x, g0, fmaf(s1y, g1, fmaf(s1z, g2, dot)));
                qx  = fmaf(s0, g0, qx);
                qy  = fmaf(s0, g1, qy);
                qz  = fmaf(s0, g2, qz);
                rx  = fmaf(f0, s1x, rx);
                ry  = fmaf(f0, s1y, ry);
                rz  = fmaf(f0, s1z, rz);
            }

            const float scale = 1.0f / (1.5f * (float)max(d, 1));
            float* F = sF + ni * FS;
            F[        lane] = a0 * scale;
            F[ 32   + lane] = ax * scale;
            F[ 64   + lane] = ay * scale;
            F[ 96   + lane] = az * scale;
            F[128   + lane] = p00 * scale;
            F[160   + lane] = dot * scale * INV_SQRT3;
            F[192   + lane] = qx * scale;   // c=0: p01
            F[224   + lane] = rx * scale;   // c=0: p10
            F[256   + lane] = qy * scale;   // c=1
            F[288   + lane] = ry * scale;
            F[320   + lane] = qz * scale;   // c=2
            F[352   + lane] = rz * scale;
        }
        __syncthreads();

        // ---------------- Phase B: f32x2 matvec, packed weights ------------
        const float2* Wp;
        int nodeBase, cc;
        if (w < 2) { Wp = sW0p; nodeBase = w * 8; cc = -1; }
        else       { cc = (w - 2) >> 1; nodeBase = ((w - 2) & 1) * 8; Wp = sW1p; }

        const float* pA = (cc < 0) ? (sF + nodeBase * FS)
                                   : (sF + nodeBase * FS + 32 + 32 * cc);
        const float* pB = (cc < 0) ? (sF + nodeBase * FS + 128)
                                   : (sF + nodeBase * FS + 192 + 64 * cc);

        unsigned long long acc[8];
        #pragma unroll
        for (int r = 0; r < 8; r++) acc[r] = 0ull;

        // region A: u in [0,32) -> weight pairs 0..15
        #pragma unroll
        for (int p = 0; p < 16; p += 2) {
            unsigned long long w01 =
                *reinterpret_cast<const unsigned long long*>(&Wp[(p    ) * 32 + lane]);
            unsigned long long w23 =
                *reinterpret_cast<const unsigned long long*>(&Wp[(p + 1) * 32 + lane]);
            #pragma unroll
            for (int r = 0; r < 8; r++) {
                ulonglong2 a = *reinterpret_cast<const ulonglong2*>(pA + r * FS + 2 * p);
                fma2(acc[r], a.x, w01);
                fma2(acc[r], a.y, w23);
            }
        }
        // region B: u in [32,96) -> weight pairs 16..47
        #pragma unroll
        for (int p = 0; p < 32; p += 2) {
            unsigned long long w01 =
                *reinterpret_cast<const unsigned long long*>(&Wp[(16 + p) * 32 + lane]);
            unsigned long long w23 =
                *reinterpret_cast<const unsigned long long*>(&Wp[(17 + p) * 32 + lane]);
            #pragma unroll
            for (int r = 0; r < 8; r++) {
                ulonglong2 a = *reinterpret_cast<const ulonglong2*>(pB + r * FS + 2 * p);
                fma2(acc[r], a.x, w01);
                fma2(acc[r], a.y, w23);
            }
        }

        #pragma unroll
        for (int r = 0; r < 8; r++) {
            int n = tile * TILE + nodeBase + r;
            if (n < N) {
                float2 f = unpack2(acc[r]);
                float res = f.x + f.y;
                if (cc < 0) out[(size_t)n * 128 + lane] = res;
                else        out[(size_t)n * 128 + 32 + 3 * lane + cc] = res;
            }
        }
    }
}

// ---------------------------------------------------------------------------
extern "C" void kernel_launch(void* const* d_in, const int* in_sizes, int n_in,
                              void* d_out, int out_size)
{
    const float* nf       = (const float*)d_in[0];
    const float* sh       = (const float*)d_in[1];
    const int*   senders  = (const int*)  d_in[2];
    const int*   recv     = (const int*)  d_in[3];
    const float* W0       = (const float*)d_in[4];
    const float* W1       = (const float*)d_in[5];
    const float* Ws0      = (const float*)d_in[6];
    const float* Ws1      = (const float*)d_in[7];
    float* out = (float*)d_out;

    int N = in_sizes[0] / 128;
    int E = in_sizes[2];

    k_fill<<<(E + 255) / 256, 256>>>(recv, E);
    k_transpose<<<(N + 7) / 8, 256>>>(nf, N);
    k_main<<<NBLK, 256>>>(sh, senders, W0, W1, Ws0, Ws1, out, N);
}

// round 5
// speedup vs baseline: 1.8637x; 1.8637x over previous
#include <cuda_runtime.h>

// ============================================================================
// Layer_70411693850653 — equivariant GNN layer, fully fused.
//
//  * messages[384:640] never consumed -> skipped
//  * agg == 1.5 * feats[:, :128] -> skip connection folded into weights
//  * scatter_mean via bucketed inverse-CSR + register gather (no float atomics)
//  * bucket stores {sender, edge} so Phase A avoids the random senders[] gather
//  * TILE=8, 36KB smem -> 6 blocks/SM (75% occ) for the latency-bound k_main
//  * Phase B: scalar FFMA + float4 smem loads (measured-best form, R1)
// ============================================================================

#define N_MAX 50000
#define CAP   32
#define TILE  8
#define FS    384
#define NBLK  888         // 6 per SM on 148 SMs

__device__ int  g_deg[N_MAX];            // zero-init at load; k_main resets
__device__ int2 g_bucket[N_MAX * CAP];   // {sender, edge}

// ---------------------------------------------------------------------------
__global__ void k_fill(const int* __restrict__ recv,
                       const int* __restrict__ senders, int E) {
    int e = blockIdx.x * blockDim.x + threadIdx.x;
    if (e < E) {
        int r = recv[e];
        int slot = atomicAdd(&g_deg[r], 1);
        if (slot < CAP) g_bucket[r * CAP + slot] = make_int2(senders[e], e);
    }
}

// ---------------------------------------------------------------------------
__global__ void __launch_bounds__(256, 6) k_main(
    const float* __restrict__ nf, const float* __restrict__ sh,
    const float* __restrict__ W0, const float* __restrict__ W1,
    const float* __restrict__ Ws0, const float* __restrict__ Ws1,
    float* __restrict__ out, int N)
{
    __shared__ __align__(16) float sW0[96 * 32];
    __shared__ __align__(16) float sW1[96 * 32];
    __shared__ __align__(16) float sF[TILE * FS];

    const float invA = 0.10206207261596575f;         // 1/sqrt(96)
    const float cB   = 1.5f * 0.17677669529663687f;  // 1.5/sqrt(32)
    const float INV_SQRT3 = 0.5773502691896258f;

    const int t    = threadIdx.x;
    const int w    = t >> 5;
    const int lane = t & 31;

    // Effective weights (skip connection folded in)
    for (int i = t; i < 96 * 32; i += 256) {
        int u = i >> 5;
        float w0 = W0[i] * invA;
        float w1 = W1[i] * invA;
        if (u < 32) { w0 = fmaf(cB, Ws0[i], w0); w1 = fmaf(cB, Ws1[i], w1); }
        sW0[i] = w0;
        sW1[i] = w1;
    }

    const int ntiles = (N + TILE - 1) / TILE;
    for (int tile = blockIdx.x; tile < ntiles; tile += gridDim.x) {
        __syncthreads();   // protect sF against previous iteration's readers

        // ---------------- Phase A: warp w owns node tile*8 + w -------------
        {
            const int n = tile * TILE + w;

            float a0 = 0.f, ax = 0.f, ay = 0.f, az = 0.f;
            float p00 = 0.f, dot = 0.f;
            float qx = 0.f, qy = 0.f, qz = 0.f;   // p01 = s0*f1
            float rx = 0.f, ry = 0.f, rz = 0.f;   // p10 = f0*s1

            int d = 0;
            if (n < N) d = g_deg[n];
            const int dc = min(d, CAP);
            if (n < N && lane == 0) g_deg[n] = 0;   // maintain zero-invariant

            int    my_s  = 0;
            float4 my_sh = make_float4(0.f, 0.f, 0.f, 0.f);
            if (lane < dc) {
                int2 se = g_bucket[n * CAP + lane];
                my_s    = se.x;
                my_sh   = *reinterpret_cast<const float4*>(sh + (size_t)se.y * 4);
            }

            for (int j = 0; j < dc; j++) {
                int   s   = __shfl_sync(0xffffffffu, my_s,    j);
                float s0  = __shfl_sync(0xffffffffu, my_sh.x, j);
                float s1x = __shfl_sync(0xffffffffu, my_sh.y, j);
                float s1y = __shfl_sync(0xffffffffu, my_sh.z, j);
                float s1z = __shfl_sync(0xffffffffu, my_sh.w, j);

                const float* row = nf + (size_t)s * 128;
                float f0 = row[lane];
                float g0 = row[32 + 3 * lane];
                float g1 = row[33 + 3 * lane];
                float g2 = row[34 + 3 * lane];

                a0 += f0; ax += g0; ay += g1; az += g2;
                p00 = fmaf(s0, f0, p00);
                dot = fmaf(s1x, g0, fmaf(s1y, g1, fmaf(s1z, g2, dot)));
                qx  = fmaf(s0, g0, qx);
                qy  = fmaf(s0, g1, qy);
                qz  = fmaf(s0, g2, qz);
                rx  = fmaf(f0, s1x, rx);
                ry  = fmaf(f0, s1y, ry);
                rz  = fmaf(f0, s1z, rz);
            }

            const float scale = 1.0f / (1.5f * (float)max(d, 1));
            float* F = sF + w * FS;
            F[        lane] = a0 * scale;
            F[ 32   + lane] = ax * scale;
            F[ 64   + lane] = ay * scale;
            F[ 96   + lane] = az * scale;
            F[128   + lane] = p00 * scale;
            F[160   + lane] = dot * scale * INV_SQRT3;
            F[192   + lane] = qx * scale;   // c=0: p01
            F[224   + lane] = rx * scale;   // c=0: p10
            F[256   + lane] = qy * scale;   // c=1
            F[288   + lane] = ry * scale;
            F[320   + lane] = qz * scale;   // c=2
            F[352   + lane] = rz * scale;
        }
        __syncthreads();

        // ---------------- Phase B: 32 rows (8 nodes x 4) / 8 warps ---------
        // warp 0,1 : scalar channel, nodes 0-3 / 4-7, weights sW0
        // warp 2-7 : vector comp c=(w-2)>>1, nodes ((w-2)&1)*4.., weights sW1
        const float* Wc;
        int nodeBase, cc;
        if (w < 2) { Wc = sW0; nodeBase = w * 4; cc = -1; }
        else       { cc = (w - 2) >> 1; nodeBase = ((w - 2) & 1) * 4; Wc = sW1; }

        const float* pA = (cc < 0) ? (sF + nodeBase * FS)
                                   : (sF + nodeBase * FS + 32 + 32 * cc);
        const float* pB = (cc < 0) ? (sF + nodeBase * FS + 128)
                                   : (sF + nodeBase * FS + 192 + 64 * cc);

        float acc[4];
        #pragma unroll
        for (int r = 0; r < 4; r++) acc[r] = 0.f;

        #pragma unroll
        for (int u = 0; u < 32; u += 4) {
            float wv0 = Wc[(u + 0) * 32 + lane];
            float wv1 = Wc[(u + 1) * 32 + lane];
            float wv2 = Wc[(u + 2) * 32 + lane];
            float wv3 = Wc[(u + 3) * 32 + lane];
            #pragma unroll
            for (int r = 0; r < 4; r++) {
                float4 a = *reinterpret_cast<const float4*>(pA + r * FS + u);
                acc[r] = fmaf(a.x, wv0, fmaf(a.y, wv1,
                         fmaf(a.z, wv2, fmaf(a.w, wv3, acc[r]))));
            }
        }
        #pragma unroll
        for (int u = 0; u < 64; u += 4) {
            float wv0 = Wc[(32 + u) * 32 + lane];
            float wv1 = Wc[(33 + u) * 32 + lane];
            float wv2 = Wc[(34 + u) * 32 + lane];
            float wv3 = Wc[(35 + u) * 32 + lane];
            #pragma unroll
            for (int r = 0; r < 4; r++) {
                float4 a = *reinterpret_cast<const float4*>(pB + r * FS + u);
                acc[r] = fmaf(a.x, wv0, fmaf(a.y, wv1,
                         fmaf(a.z, wv2, fmaf(a.w, wv3, acc[r]))));
            }
        }

        #pragma unroll
        for (int r = 0; r < 4; r++) {
            int n = tile * TILE + nodeBase + r;
            if (n < N) {
                if (cc < 0) out[(size_t)n * 128 + lane] = acc[r];
                else        out[(size_t)n * 128 + 32 + 3 * lane + cc] = acc[r];
            }
        }
    }
}

// ---------------------------------------------------------------------------
extern "C" void kernel_launch(void* const* d_in, const int* in_sizes, int n_in,
                              void* d_out, int out_size)
{
    const float* nf       = (const float*)d_in[0];
    const float* sh       = (const float*)d_in[1];
    const int*   senders  = (const int*)  d_in[2];
    const int*   recv     = (const int*)  d_in[3];
    const float* W0       = (const float*)d_in[4];
    const float* W1       = (const float*)d_in[5];
    const float* Ws0      = (const float*)d_in[6];
    const float* Ws1      = (const float*)d_in[7];
    float* out = (float*)d_out;

    int N = in_sizes[0] / 128;
    int E = in_sizes[2];

    k_fill<<<(E + 511) / 512, 512>>>(recv, senders, E);
    k_main<<<NBLK, 256>>>(nf, sh, W0, W1, Ws0, Ws1, out, N);
}